// round 9
// baseline (speedup 1.0000x reference)
#include <cuda_runtime.h>

typedef unsigned long long u64;

#define B_TOTAL  32768
#define NUM_MID  6
#define PPB      16          // patches per block (8 pairs)
#define NPAIR    8
#define NTHREADS 256         // warp = pair; lanes 25..31 idle in conv phases

// Plane: 25 pair-packed positions, contiguous u64[25], stride 52 floats (16B aligned)
#define PLANE_F   52
#define PLANE_U   26
#define H_BUF     (NPAIR*25*PLANE_F)        // 10400 floats
#define W_BUF     5625                      // [25oc][25ic][9]
#define WPOST_OFF 1800                      // conv0 occupies [0,1800); wpost at [1800,3150)
#define SMEM_FLOATS (H_BUF + W_BUF + 32 + 2*NPAIR*18)
#define SMEM_BYTES  (SMEM_FLOATS*4)

// ---- f32x2 helpers ----
__device__ __forceinline__ u64 f2pack(float lo, float hi) {
    u64 r; asm("mov.b64 %0,{%1,%2};" : "=l"(r) : "f"(lo), "f"(hi)); return r;
}
__device__ __forceinline__ u64 f2bcast(float v) { return f2pack(v, v); }
__device__ __forceinline__ void f2unpack(u64 a, float& lo, float& hi) {
    asm("mov.b64 {%0,%1},%2;" : "=f"(lo), "=f"(hi) : "l"(a));
}
__device__ __forceinline__ u64 f2fma(u64 a, u64 b, u64 c) {
    u64 d; asm("fma.rn.f32x2 %0,%1,%2,%3;" : "=l"(d) : "l"(a), "l"(b), "l"(c)); return d;
}

// Tap-loop conv: whole ic-plane (25 u64) in registers, 9 taps, per tap up to 25
// independent FMAs on distinct accumulators. All smem loads warp-broadcast.
template<int CIN>
__device__ __forceinline__ void conv_accum(const float* __restrict__ hin,
                                           const float* __restrict__ wrow,
                                           float bias,
                                           u64 acc[25])
{
    const u64 b2 = f2bcast(bias);
    #pragma unroll
    for (int i = 0; i < 25; i++) acc[i] = b2;

    #pragma unroll 1
    for (int ic = 0; ic < CIN; ic++) {
        const u64* pp = (const u64*)(hin + ic * PLANE_F);
        u64 pos[25];
        #pragma unroll
        for (int k = 0; k < 12; k++) {
            ulonglong2 q = ((const ulonglong2*)pp)[k];
            pos[2*k] = q.x; pos[2*k+1] = q.y;
        }
        pos[24] = pp[24];

        const float* wp = wrow + ic * 9;
        #pragma unroll
        for (int dy = 0; dy < 3; dy++) {
            #pragma unroll
            for (int dx = 0; dx < 3; dx++) {
                const u64 w2 = f2bcast(wp[dy*3 + dx]);
                #pragma unroll
                for (int y = 0; y < 5; y++) {
                    const int iy = y + dy - 1;
                    if (iy >= 0 && iy < 5) {
                        #pragma unroll
                        for (int x = 0; x < 5; x++) {
                            const int ix = x + dx - 1;
                            if (ix >= 0 && ix < 5)
                                acc[y*5 + x] = f2fma(w2, pos[iy*5 + ix], acc[y*5 + x]);
                        }
                    }
                }
            }
        }
    }
}

__device__ __forceinline__ void relu_store(float* __restrict__ hout, const u64 acc[25])
{
    u64* op = (u64*)hout;
    #pragma unroll
    for (int k = 0; k < 12; k++) {
        float l0, h0, l1, h1;
        f2unpack(acc[2*k],   l0, h0);
        f2unpack(acc[2*k+1], l1, h1);
        ((ulonglong2*)op)[k] = make_ulonglong2(
            f2pack(fmaxf(l0,0.f), fmaxf(h0,0.f)),
            f2pack(fmaxf(l1,0.f), fmaxf(h1,0.f)));
    }
    {
        float l, h; f2unpack(acc[24], l, h);
        op[24] = f2pack(fmaxf(l,0.f), fmaxf(h,0.f));
    }
}

// Coalesced LDG prefetch of next layer's 5625 weights (all 256 threads)
#define WCHUNK 21
#define WTAIL  (W_BUF - WCHUNK*NTHREADS)   // 249
__device__ __forceinline__ void load_w_regs(const float* __restrict__ wg, int tid, float wtmp[WCHUNK+1]) {
    #pragma unroll
    for (int k = 0; k < WCHUNK; k++) wtmp[k] = wg[tid + k*NTHREADS];
    wtmp[WCHUNK] = (tid < WTAIL) ? wg[tid + WCHUNK*NTHREADS] : 0.0f;
}
__device__ __forceinline__ void store_w_smem(float* __restrict__ wbuf, int tid, const float wtmp[WCHUNK+1]) {
    #pragma unroll
    for (int k = 0; k < WCHUNK; k++) wbuf[tid + k*NTHREADS] = wtmp[k];
    if (tid < WTAIL) wbuf[tid + WCHUNK*NTHREADS] = wtmp[WCHUNK];
}

__global__ __launch_bounds__(NTHREADS, 2)
void Kpcnn_49160195670356_kernel(const float* __restrict__ gin,
                                 const float* __restrict__ w0,
                                 const float* __restrict__ b0,
                                 const float* __restrict__ wmid,
                                 const float* __restrict__ bmid,
                                 const float* __restrict__ wlast,
                                 const float* __restrict__ blast,
                                 const float* __restrict__ wpost,
                                 const float* __restrict__ bpost,
                                 float* __restrict__ gout)
{
    extern __shared__ float smem[];
    float* hbuf   = smem;                // H_BUF
    float* wbuf   = hbuf + H_BUF;        // W_BUF
    float* bbuf   = wbuf + W_BUF;        // 32
    float* colorsS= bbuf + 32;           // [2 half][NPAIR][18]

    const int tid  = threadIdx.x;
    const int pair = tid >> 5;           // warp index = pair
    const int oc   = tid & 31;
    const bool act = (oc < 25);
    const long pg  = (long)blockIdx.x * PPB;

    float* myplane = hbuf + pair * 25 * PLANE_F;

    // ---- stage input (pair-interleaved), conv0 weights, wpost, b0 ----
    for (int i = tid; i < PPB * 200; i += NTHREADS) {
        const int patch = i / 200;
        const int rem   = i % 200;
        const int c     = rem / 25;
        const int pos   = rem % 25;
        const float v = gin[(pg + patch) * 200 + rem];
        hbuf[((patch >> 1) * 25 + c) * PLANE_F + pos * 2 + (patch & 1)] = v;
    }
    for (int i = tid; i < 25 * 8 * 9; i += NTHREADS) wbuf[i] = w0[i];
    for (int i = tid; i < 18 * 75; i += NTHREADS) wbuf[WPOST_OFF + i] = wpost[i];
    if (tid < 25) bbuf[tid] = b0[tid];
    __syncthreads();

    // ---- colors (VALID 5x5 conv on input ch 0..2): 3 indep accumulators ----
    if (act && oc < 18) {
        const float* wp = wbuf + WPOST_OFF + oc * 75;
        u64 a0 = f2bcast(__ldg(bpost + oc));
        u64 a1 = f2bcast(0.0f);
        u64 a2 = f2bcast(0.0f);
        const u64* ip0 = (const u64*)(myplane + 0 * PLANE_F);
        const u64* ip1 = (const u64*)(myplane + 1 * PLANE_F);
        const u64* ip2 = (const u64*)(myplane + 2 * PLANE_F);
        #pragma unroll
        for (int k = 0; k < 25; k++) {
            a0 = f2fma(f2bcast(wp[k]),      ip0[k], a0);
            a1 = f2fma(f2bcast(wp[25 + k]), ip1[k], a1);
            a2 = f2fma(f2bcast(wp[50 + k]), ip2[k], a2);
        }
        float lo0, hi0, lo1, hi1, lo2, hi2;
        f2unpack(a0, lo0, hi0); f2unpack(a1, lo1, hi1); f2unpack(a2, lo2, hi2);
        colorsS[pair * 18 + oc] = lo0 + lo1 + lo2;
        colorsS[NPAIR * 18 + pair * 18 + oc] = hi0 + hi1 + hi2;
    }

    // ---- conv0: 8ch -> 25ch, in place ----
    {
        u64 acc[25];
        if (act)
            conv_accum<8>(myplane, wbuf + oc * 72, bbuf[oc], acc);
        __syncthreads();   // reads of input (incl. colors) + wbuf done

        float wtmp[WCHUNK+1];
        load_w_regs(wmid, tid, wtmp);
        if (act) relu_store(myplane + oc * PLANE_F, acc);
        store_w_smem(wbuf, tid, wtmp);
        if (tid < 25) bbuf[tid] = bmid[tid];
        __syncthreads();
    }

    // ---- mid layers: accum; bar; {store + prefetch next weights}; bar ----
    #pragma unroll 1
    for (int layer = 0; layer < NUM_MID; layer++) {
        u64 acc[25];
        if (act)
            conv_accum<25>(myplane, wbuf + oc * 225, bbuf[oc], acc);
        __syncthreads();

        if (layer < NUM_MID - 1) {
            float wtmp[WCHUNK+1];
            load_w_regs(wmid + (long)(layer + 1) * W_BUF, tid, wtmp);
            if (act) relu_store(myplane + oc * PLANE_F, acc);
            store_w_smem(wbuf, tid, wtmp);
            if (tid < 25) bbuf[tid] = bmid[(layer + 1) * 25 + tid];
        } else {
            if (act) relu_store(myplane + oc * PLANE_F, acc);
            // stage wlast pre-packed pairs: u64[(w*25+ic)*10 + t]
            for (int i = tid; i < 6 * 25 * 9; i += NTHREADS) {
                const int row = i / 9, t = i % 9;
                const float v = wlast[i];
                wbuf[(row * 10 + t) * 2 + 0] = v;
                wbuf[(row * 10 + t) * 2 + 1] = v;
            }
            if (tid < 6) bbuf[tid] = blast[tid];
        }
        __syncthreads();
    }

    // ---- last conv (25->6) per position + softmax + einsum ----
    if (act) {
        const int j = oc;
        const int y = j / 5, x = j % 5;

        int  off[9];
        bool inb[9];
        #pragma unroll
        for (int dy = 0; dy < 3; dy++)
            #pragma unroll
            for (int dx = 0; dx < 3; dx++) {
                const int iy = y + dy - 1, ix = x + dx - 1;
                const int t = dy * 3 + dx;
                inb[t] = (iy >= 0 && iy < 5 && ix >= 0 && ix < 5);
                off[t] = inb[t] ? (iy * 5 + ix) : 0;
            }

        u64 s[6];
        #pragma unroll
        for (int w = 0; w < 6; w++) s[w] = f2bcast(bbuf[w]);

        #pragma unroll 1
        for (int ic = 0; ic < 25; ic++) {
            const u64* hp = (const u64*)(myplane + ic * PLANE_F);
            u64 v[9];
            #pragma unroll
            for (int t = 0; t < 9; t++) v[t] = inb[t] ? hp[off[t]] : 0ULL;
            #pragma unroll
            for (int t = 0; t < 9; t++) {
                #pragma unroll
                for (int w = 0; w < 6; w++) {
                    const u64 wl = ((const u64*)wbuf)[(w * 25 + ic) * 10 + t];
                    s[w] = f2fma(wl, v[t], s[w]);
                }
            }
        }

        #pragma unroll
        for (int half = 0; half < 2; half++) {
            float sv[6];
            #pragma unroll
            for (int w = 0; w < 6; w++) {
                float lo, hi; f2unpack(s[w], lo, hi);
                sv[w] = half ? hi : lo;
            }
            float m = sv[0];
            #pragma unroll
            for (int w = 1; w < 6; w++) m = fmaxf(m, sv[w]);
            float e[6], sum = 0.0f;
            #pragma unroll
            for (int w = 0; w < 6; w++) { e[w] = __expf(sv[w] - m); sum += e[w]; }
            const float inv = 1.0f / sum;

            const float* col = colorsS + half * (NPAIR * 18) + pair * 18;
            const long ob = (pg + 2 * pair + half) * 75;
            #pragma unroll
            for (int c = 0; c < 3; c++) {
                float r = 0.0f;
                #pragma unroll
                for (int w = 0; w < 6; w++) r = fmaf(col[c * 6 + w], e[w], r);
                gout[ob + c * 25 + j] = r * inv;
            }
        }
    }
}

extern "C" void kernel_launch(void* const* d_in, const int* in_sizes, int n_in,
                              void* d_out, int out_size)
{
    const float* gin   = (const float*)d_in[0];
    const float* w0    = (const float*)d_in[1];
    const float* b0    = (const float*)d_in[2];
    const float* wmid  = (const float*)d_in[3];
    const float* bmid  = (const float*)d_in[4];
    const float* wlast = (const float*)d_in[5];
    const float* blast = (const float*)d_in[6];
    const float* wpost = (const float*)d_in[7];
    const float* bpost = (const float*)d_in[8];
    float* gout = (float*)d_out;

    cudaFuncSetAttribute(Kpcnn_49160195670356_kernel,
                         cudaFuncAttributeMaxDynamicSharedMemorySize, SMEM_BYTES);

    Kpcnn_49160195670356_kernel<<<B_TOTAL / PPB, NTHREADS, SMEM_BYTES>>>(
        gin, w0, b0, wmid, bmid, wlast, blast, wpost, bpost, gout);
}